// round 15
// baseline (speedup 1.0000x reference)
#include <cuda_runtime.h>
#include <cuda_fp16.h>
#include <cstdint>

#define NN 8192
#define DD 64
#define EK 262144
#define EHK 262144
#define ETOT (EHK + EK)
#define TAB 2048
#define MB 148                 // matvec worker blocks (1 per SM — saturates DRAM)
#define EB 740                 // edge worker blocks (5 per SM)
#define EWARPS (EB * 8)        // 5920 edge warps

// Scratch (device globals: allocation-free)
__device__ float  g_sk[NN * DD];    // normalized state_K (fp32, for fin)
__device__ __half g_skh[NN * DD];   // normalized state_K (fp16, for edge phase)
__device__ float  g_g[NN];          // tanh(state_H)
__device__ float  g_fK[NN * DD];    // f_K edge accumulator (fp32, exact)
__device__ float  g_fHa[NN];        // f_H edge accumulator
__device__ float2 g_tab2[TAB + 1];  // dE table: (f(s_i), f(s_{i+1}))

// No "memory" clobber: g_fK/g_fHa are write-only in mega.
__device__ __forceinline__ void red4(float* p, float a, float b, float c, float d) {
    asm volatile("red.global.add.v4.f32 [%0], {%1,%2,%3,%4};"
                 :: "l"(p), "f"(a), "f"(b), "f"(c), "f"(d));
}
__device__ __forceinline__ void red1(float* p, float a) {
    asm volatile("red.global.add.f32 [%0], %1;" :: "l"(p), "f"(a));
}
__device__ __forceinline__ float warp_sum(float v) {
    #pragma unroll
    for (int o = 16; o; o >>= 1) v += __shfl_xor_sync(0xFFFFFFFFu, v, o);
    return v;
}

// --- prep: normalize sk (fp32 + fp16 mirror), g=tanh(sH), zero accum, table.
__global__ void prep_kernel(const float* __restrict__ sH, const float* __restrict__ sK,
                            const float* __restrict__ w1, const float* __restrict__ b1,
                            const float* __restrict__ w2) {
    int warp = threadIdx.x >> 5, lane = threadIdx.x & 31;
    int row = blockIdx.x * 8 + warp;
    float2 v = ((const float2*)(sK + row * DD))[lane];
    float ss = warp_sum(v.x * v.x + v.y * v.y);
    float inv = rsqrtf(ss);
    float nx = v.x * inv, ny = v.y * inv;
    ((float2*)(g_sk + row * DD))[lane] = make_float2(nx, ny);
    ((__half2*)(g_skh + row * DD))[lane] = __floats2half2_rn(nx, ny);
    if (lane == 0) g_g[row] = tanhf(sH[row]);

    int gt = blockIdx.x * 256 + threadIdx.x;          // 0..262143
    if (gt < NN * DD / 4) ((float4*)g_fK)[gt] = make_float4(0.f, 0.f, 0.f, 0.f);
    if (gt < NN / 4)      ((float4*)g_fHa)[gt] = make_float4(0.f, 0.f, 0.f, 0.f);

    int entry = blockIdx.x * 8 + warp;                // warp-per-table-entry
    if (entry <= TAB) {
        float s0 = entry * (2.0f / TAB) - 1.0f;
        float s1 = s0 + (2.0f / TAB);
        float wa = __ldg(w1 + lane),      ba = __ldg(b1 + lane),      ca = __ldg(w2 + lane);
        float wb = __ldg(w1 + lane + 32), bb = __ldg(b1 + lane + 32), cb = __ldg(w2 + lane + 32);
        float fa = warp_sum(tanhf(s0 * wa + ba) * ca + tanhf(s0 * wb + bb) * cb);
        float fb = warp_sum(tanhf(s1 * wa + ba) * ca + tanhf(s1 * wb + bb) * cb);
        if (lane == 0) g_tab2[entry] = make_float2(fa, fb);
    }
}

// --- mega: persistent workers. Blocks 0..MB-1: matvec rows (grid-stride).
//     Blocks MB..MB+EB-1: edges (warp grid-stride over EHK+EK jobs).
__global__ __launch_bounds__(256, 6) void mega_kernel(
    const float* __restrict__ sH, const float* __restrict__ W,
    const int* __restrict__ indK, const int* __restrict__ indHK,
    float* __restrict__ out)
{
    int lane = threadIdx.x & 31, warp = threadIdx.x >> 5;

    if (blockIdx.x < MB) {
        // ---- matvec worker: rows blockIdx.x, +MB, ... keeps DRAM saturated.
        __shared__ float rr[8];
        const float4* g4 = (const float4*)g_g;
        for (int row = blockIdx.x; row < NN; row += MB) {
            const float4* Wr = (const float4*)(W + (size_t)row * NN);
            float acc = 0.f;
            #pragma unroll
            for (int it = 0; it < 8; it++) {
                int k = threadIdx.x + it * 256;
                float4 w = __ldcs(Wr + k);     // stream: don't pollute L2
                float4 g = g4[k];
                acc += w.x * g.x + w.y * g.y + w.z * g.z + w.w * g.w;
            }
            acc = warp_sum(acc);
            if (lane == 0) rr[warp] = acc;
            __syncthreads();
            if (threadIdx.x == 0) {
                float v = rr[0] + rr[1] + rr[2] + rr[3] + rr[4] + rr[5] + rr[6] + rr[7];
                out[row] = -sH[row] + v;
            }
            __syncthreads();
        }
        return;
    }

    // ---- edge worker: warp-per-edge, half-warp per endpoint, fp16 gather.
    int c = lane & 15;                    // 8-byte chunk (4 halves) within fp16 row
    int wg = (blockIdx.x - MB) * 8 + warp;
    #pragma unroll 2
    for (int e = wg; e < ETOT; e += EWARPS) {
        bool isHK = e < EHK;
        int2 ij = isHK ? __ldg((const int2*)indHK + e)
                       : __ldg((const int2*)indK + (e - EHK));
        int myRow = (lane < 16) ? ij.x : ij.y;
        uint2 vh = __ldg((const uint2*)(g_skh + myRow * DD) + c);  // 4 halves of my row
        uint2 wh;                          // partner row chunk
        wh.x = __shfl_xor_sync(0xFFFFFFFFu, vh.x, 16);
        wh.y = __shfl_xor_sync(0xFFFFFFFFu, vh.y, 16);
        float2 va = __half22float2(*(const __half2*)&vh.x);
        float2 vb = __half22float2(*(const __half2*)&vh.y);
        float2 wa = __half22float2(*(const __half2*)&wh.x);
        float2 wb = __half22float2(*(const __half2*)&wh.y);
        float d = va.x * wa.x + va.y * wa.y + vb.x * wb.x + vb.y * wb.y;
        d += __shfl_xor_sync(0xFFFFFFFFu, d, 1);
        d += __shfl_xor_sync(0xFFFFFFFFu, d, 2);
        d += __shfl_xor_sync(0xFFFFFFFFu, d, 4);
        d += __shfl_xor_sync(0xFFFFFFFFu, d, 8);   // s = <row_i, row_j>
        float coef;
        if (isHK) {
            float gm = __ldg(g_g + myRow);
            float gp = __shfl_xor_sync(0xFFFFFFFFu, gm, 16);
            if ((lane & 15) == 0)                       // lanes 0 and 16
                red1(g_fHa + myRow, d * gp * 0.5f);     // /KAPPA_H
            coef = -0.5f * gm * gp;                     // -G/KAPPA_K
        } else {
            float t = (fminf(fmaxf(d, -1.f), 1.f) + 1.f) * (TAB * 0.5f);
            int i0 = min((int)t, TAB - 1);
            float f = t - (float)i0;
            float2 tt = __ldg(g_tab2 + i0);
            coef = tt.x + (tt.y - tt.x) * f;            // dE(s)
        }
        // endpoint myRow accumulates coef * partner_row chunk (4 floats), fp32 red
        red4(g_fK + myRow * DD + c * 4,
             coef * wa.x, coef * wa.y, coef * wb.x, coef * wb.y);
    }
}

// --- finalize: f_H += fHacc; f_K = -acc + sk*<sk,acc> + sk @ (omega-omega^T)/2.
__global__ void fin_kernel(const float* __restrict__ omega, float* __restrict__ out) {
    __shared__ float A[DD * DD];      // antisymmetrized omega
    __shared__ float srow[8 * DD];
    for (int k = threadIdx.x; k < DD * DD; k += 256) {
        int rI = k >> 6, cc = k & 63;
        A[k] = 0.5f * (omega[k] - omega[cc * DD + rI]);
    }
    __syncthreads();
    int warp = threadIdx.x >> 5, lane = threadIdx.x & 31;
    int row = blockIdx.x * 8 + warp;
    if (lane == 0) out[row] += g_fHa[row];            // finish f_H
    float2 skv = ((const float2*)(g_sk + row * DD))[lane];
    float2 fv  = ((const float2*)(g_fK + row * DD))[lane];
    float d = warp_sum(skv.x * fv.x + skv.y * fv.y);
    ((float2*)(srow + warp * DD))[lane] = skv;
    __syncwarp();
    const float* sr = srow + warp * DD;
    const float2* A2 = (const float2*)A;
    float m0 = 0.f, m1 = 0.f;
    #pragma unroll
    for (int k = 0; k < DD; k++) {
        float sv = sr[k];
        float2 av = A2[k * 32 + lane];
        m0 += sv * av.x;
        m1 += sv * av.y;
    }
    float o0 = -fv.x + skv.x * d + m0;
    float o1 = -fv.y + skv.y * d + m1;
    ((float2*)(out + NN + row * DD))[lane] = make_float2(o0, o1);
}

extern "C" void kernel_launch(void* const* d_in, const int* in_sizes, int n_in,
                              void* d_out, int out_size) {
    const float* sH   = (const float*)d_in[0];
    const float* sK   = (const float*)d_in[1];
    const float* WH   = (const float*)d_in[2];
    const float* om   = (const float*)d_in[3];
    const float* w1   = (const float*)d_in[4];
    const float* b1   = (const float*)d_in[5];
    const float* w2   = (const float*)d_in[6];
    const int*  indK  = (const int*)d_in[7];
    const int*  indHK = (const int*)d_in[8];
    float* out = (float*)d_out;

    prep_kernel<<<NN / 8, 256>>>(sH, sK, w1, b1, w2);
    mega_kernel<<<MB + EB, 256>>>(sH, WH, indK, indHK, out);
    fin_kernel<<<NN / 8, 256>>>(om, out);
}

// round 16
// speedup vs baseline: 1.4562x; 1.4562x over previous
#include <cuda_runtime.h>
#include <cuda_fp16.h>
#include <cstdint>

#define NN 8192
#define DD 64
#define EK 262144
#define EHK 262144
#define ETOT (EHK + EK)
#define TAB 2048
#define MB 296                 // matvec worker blocks (2 per SM)
#define EB 592                 // edge worker blocks (4 per SM)
#define EWARPS (EB * 8)        // 4736 edge warps

// Scratch (device globals: allocation-free)
__device__ float  g_sk[NN * DD];    // normalized state_K (fp32, for fin)
__device__ __half g_skh[NN * DD];   // normalized state_K (fp16, for edge phase)
__device__ float  g_g[NN];          // tanh(state_H)
__device__ float  g_fK[NN * DD];    // f_K edge accumulator (fp32, exact)
__device__ float  g_fHa[NN];        // f_H edge accumulator
__device__ float2 g_tab2[TAB + 1];  // dE table: (f(s_i), f(s_{i+1}))

// No "memory" clobber: targets are write-only in mega.
__device__ __forceinline__ void red4(float* p, float a, float b, float c, float d) {
    asm volatile("red.global.add.v4.f32 [%0], {%1,%2,%3,%4};"
                 :: "l"(p), "f"(a), "f"(b), "f"(c), "f"(d));
}
__device__ __forceinline__ void red1(float* p, float a) {
    asm volatile("red.global.add.f32 [%0], %1;" :: "l"(p), "f"(a));
}
__device__ __forceinline__ float warp_sum(float v) {
    #pragma unroll
    for (int o = 16; o; o >>= 1) v += __shfl_xor_sync(0xFFFFFFFFu, v, o);
    return v;
}

// --- prep: normalize sk (fp32 + fp16 mirror), g=tanh(sH), zero accum,
//     out[0..NN) = -sH (matvec base), build dE table.
__global__ void prep_kernel(const float* __restrict__ sH, const float* __restrict__ sK,
                            const float* __restrict__ w1, const float* __restrict__ b1,
                            const float* __restrict__ w2, float* __restrict__ out) {
    int warp = threadIdx.x >> 5, lane = threadIdx.x & 31;
    int row = blockIdx.x * 8 + warp;
    float2 v = ((const float2*)(sK + row * DD))[lane];
    float ss = warp_sum(v.x * v.x + v.y * v.y);
    float inv = rsqrtf(ss);
    float nx = v.x * inv, ny = v.y * inv;
    ((float2*)(g_sk + row * DD))[lane] = make_float2(nx, ny);
    ((__half2*)(g_skh + row * DD))[lane] = __floats2half2_rn(nx, ny);
    if (lane == 0) g_g[row] = tanhf(sH[row]);
    if (lane == 1) out[row] = -sH[row];               // matvec base (out is poisoned)

    int gt = blockIdx.x * 256 + threadIdx.x;          // 0..262143
    if (gt < NN * DD / 4) ((float4*)g_fK)[gt] = make_float4(0.f, 0.f, 0.f, 0.f);
    if (gt < NN / 4)      ((float4*)g_fHa)[gt] = make_float4(0.f, 0.f, 0.f, 0.f);

    int entry = blockIdx.x * 8 + warp;                // warp-per-table-entry
    if (entry <= TAB) {
        float s0 = entry * (2.0f / TAB) - 1.0f;
        float s1 = s0 + (2.0f / TAB);
        float wa = __ldg(w1 + lane),      ba = __ldg(b1 + lane),      ca = __ldg(w2 + lane);
        float wb = __ldg(w1 + lane + 32), bb = __ldg(b1 + lane + 32), cb = __ldg(w2 + lane + 32);
        float fa = warp_sum(tanhf(s0 * wa + ba) * ca + tanhf(s0 * wb + bb) * cb);
        float fb = warp_sum(tanhf(s1 * wa + ba) * ca + tanhf(s1 * wb + bb) * cb);
        if (lane == 0) g_tab2[entry] = make_float2(fa, fb);
    }
}

// --- mega: persistent workers. Blocks 0..MB-1: matvec rows (grid-stride,
//     sync-free finish via red1). Blocks MB..MB+EB-1: edges.
__global__ __launch_bounds__(256, 6) void mega_kernel(
    const float* __restrict__ sH, const float* __restrict__ W,
    const int* __restrict__ indK, const int* __restrict__ indHK,
    float* __restrict__ out)
{
    int lane = threadIdx.x & 31, warp = threadIdx.x >> 5;

    if (blockIdx.x < MB) {
        // ---- matvec worker: no __syncthreads — each warp red1's its partial,
        //      so the load stream never drains between rows.
        const float4* g4 = (const float4*)g_g;
        for (int row = blockIdx.x; row < NN; row += MB) {
            const float4* Wr = (const float4*)(W + (size_t)row * NN);
            float acc = 0.f;
            #pragma unroll
            for (int it = 0; it < 8; it++) {
                int k = threadIdx.x + it * 256;
                float4 w = __ldcs(Wr + k);     // stream: don't pollute L2
                float4 g = g4[k];
                acc += w.x * g.x + w.y * g.y + w.z * g.z + w.w * g.w;
            }
            acc = warp_sum(acc);
            if (lane == 0) red1(out + row, acc);   // base -sH written by prep
        }
        return;
    }

    // ---- edge worker: warp-per-edge, half-warp per endpoint, fp16 gather.
    int c = lane & 15;                    // 8-byte chunk (4 halves) within fp16 row
    int wg = (blockIdx.x - MB) * 8 + warp;
    #pragma unroll 2
    for (int e = wg; e < ETOT; e += EWARPS) {
        bool isHK = e < EHK;
        int2 ij = isHK ? __ldg((const int2*)indHK + e)
                       : __ldg((const int2*)indK + (e - EHK));
        int myRow = (lane < 16) ? ij.x : ij.y;
        uint2 vh = __ldg((const uint2*)(g_skh + myRow * DD) + c);  // 4 halves of my row
        uint2 wh;                          // partner row chunk
        wh.x = __shfl_xor_sync(0xFFFFFFFFu, vh.x, 16);
        wh.y = __shfl_xor_sync(0xFFFFFFFFu, vh.y, 16);
        float2 va = __half22float2(*(const __half2*)&vh.x);
        float2 vb = __half22float2(*(const __half2*)&vh.y);
        float2 wa = __half22float2(*(const __half2*)&wh.x);
        float2 wb = __half22float2(*(const __half2*)&wh.y);
        float d = va.x * wa.x + va.y * wa.y + vb.x * wb.x + vb.y * wb.y;
        d += __shfl_xor_sync(0xFFFFFFFFu, d, 1);
        d += __shfl_xor_sync(0xFFFFFFFFu, d, 2);
        d += __shfl_xor_sync(0xFFFFFFFFu, d, 4);
        d += __shfl_xor_sync(0xFFFFFFFFu, d, 8);   // s = <row_i, row_j>
        float coef;
        if (isHK) {
            float gm = __ldg(g_g + myRow);
            float gp = __shfl_xor_sync(0xFFFFFFFFu, gm, 16);
            if ((lane & 15) == 0)                       // lanes 0 and 16
                red1(g_fHa + myRow, d * gp * 0.5f);     // /KAPPA_H
            coef = -0.5f * gm * gp;                     // -G/KAPPA_K
        } else {
            float t = (fminf(fmaxf(d, -1.f), 1.f) + 1.f) * (TAB * 0.5f);
            int i0 = min((int)t, TAB - 1);
            float f = t - (float)i0;
            float2 tt = __ldg(g_tab2 + i0);
            coef = tt.x + (tt.y - tt.x) * f;            // dE(s)
        }
        // endpoint myRow accumulates coef * partner_row chunk (4 floats), fp32 red
        red4(g_fK + myRow * DD + c * 4,
             coef * wa.x, coef * wa.y, coef * wb.x, coef * wb.y);
    }
}

// --- finalize: f_H += fHacc; f_K = -acc + sk*<sk,acc> + sk @ (omega-omega^T)/2.
__global__ void fin_kernel(const float* __restrict__ omega, float* __restrict__ out) {
    __shared__ float A[DD * DD];      // antisymmetrized omega
    __shared__ float srow[8 * DD];
    for (int k = threadIdx.x; k < DD * DD; k += 256) {
        int rI = k >> 6, cc = k & 63;
        A[k] = 0.5f * (omega[k] - omega[cc * DD + rI]);
    }
    __syncthreads();
    int warp = threadIdx.x >> 5, lane = threadIdx.x & 31;
    int row = blockIdx.x * 8 + warp;
    if (lane == 0) out[row] += g_fHa[row];            // finish f_H
    float2 skv = ((const float2*)(g_sk + row * DD))[lane];
    float2 fv  = ((const float2*)(g_fK + row * DD))[lane];
    float d = warp_sum(skv.x * fv.x + skv.y * fv.y);
    ((float2*)(srow + warp * DD))[lane] = skv;
    __syncwarp();
    const float* sr = srow + warp * DD;
    const float2* A2 = (const float2*)A;
    float m0 = 0.f, m1 = 0.f;
    #pragma unroll
    for (int k = 0; k < DD; k++) {
        float sv = sr[k];
        float2 av = A2[k * 32 + lane];
        m0 += sv * av.x;
        m1 += sv * av.y;
    }
    float o0 = -fv.x + skv.x * d + m0;
    float o1 = -fv.y + skv.y * d + m1;
    ((float2*)(out + NN + row * DD))[lane] = make_float2(o0, o1);
}

extern "C" void kernel_launch(void* const* d_in, const int* in_sizes, int n_in,
                              void* d_out, int out_size) {
    const float* sH   = (const float*)d_in[0];
    const float* sK   = (const float*)d_in[1];
    const float* WH   = (const float*)d_in[2];
    const float* om   = (const float*)d_in[3];
    const float* w1   = (const float*)d_in[4];
    const float* b1   = (const float*)d_in[5];
    const float* w2   = (const float*)d_in[6];
    const int*  indK  = (const int*)d_in[7];
    const int*  indHK = (const int*)d_in[8];
    float* out = (float*)d_out;

    prep_kernel<<<NN / 8, 256>>>(sH, sK, w1, b1, w2, out);
    mega_kernel<<<MB + EB, 256>>>(sH, WH, indK, indHK, out);
    fin_kernel<<<NN / 8, 256>>>(om, out);
}